// round 4
// baseline (speedup 1.0000x reference)
#include <cuda_runtime.h>
#include <cuda_fp16.h>
#include <math.h>

#define BB 8
#define SS 4096
#define DD 768
#define MM 64
#define FF 3072
#define HH 12
#define HD 64
#define EPSF 1e-5f

typedef unsigned long long ull;

__device__ __forceinline__ ull pk2(float lo, float hi) {
    ull r;
    asm("mov.b64 %0, {%1, %2};" : "=l"(r) : "f"(lo), "f"(hi));
    return r;
}
__device__ __forceinline__ void upk2(ull v, float& lo, float& hi) {
    asm("mov.b64 {%0, %1}, %2;" : "=f"(lo), "=f"(hi) : "l"(v));
}
#define FMA2(a, x, y) asm("fma.rn.f32x2 %0, %1, %2, %0;" : "+l"(a) : "l"(x), "l"(y))

// ---------------- scratch -----------------------------------------------------
__device__ float  g_sl[MM * DD];
__device__ float  g_xn[BB * SS * DD];
__device__ float  g_rn[BB * SS];
__device__ __half g_lh[(size_t)BB * HH * MM * SS];
__device__ float  g_rmax[BB * HH * MM];
__device__ float  g_rsum[BB * HH * MM];
__device__ float  g_y[BB * MM * DD];
__device__ float  g_hid[(size_t)BB * MM * FF];
__device__ float  g_y2[BB * MM * DD];

// ---------------- K0: slots ---------------------------------------------------
__global__ void k_slots(const float* __restrict__ slots, const float* __restrict__ scale) {
    int m = blockIdx.x, tid = threadIdx.x;
    __shared__ float red[8];
    float ss = 0.f;
    for (int i = tid; i < DD; i += 256) { float v = slots[m * DD + i]; ss += v * v; }
    for (int o = 16; o; o >>= 1) ss += __shfl_down_sync(~0u, ss, o);
    if ((tid & 31) == 0) red[tid >> 5] = ss;
    __syncthreads();
    if (tid == 0) { float s = 0; for (int i = 0; i < 8; i++) s += red[i]; red[0] = s; }
    __syncthreads();
    float inv = scale[m] / fmaxf(sqrtf(red[0]), EPSF);
    for (int i = tid; i < DD; i += 256) g_sl[m * DD + i] = slots[m * DD + i] * inv;
}

// ---------------- K1: rmsnorm + l2, warp-per-token ------------------------------
__global__ void __launch_bounds__(256) k_norm(const float* __restrict__ x,
                                              const float* __restrict__ nw) {
    int t = blockIdx.x * 8 + (threadIdx.x >> 5);
    int lane = threadIdx.x & 31;
    const float4* xr = (const float4*)(x + (size_t)t * DD);
    const float4* wr = (const float4*)nw;
    float4 v[6];
    float ss = 0.f;
#pragma unroll
    for (int j = 0; j < 6; j++) {
        v[j] = xr[lane + 32 * j];
        ss += v[j].x * v[j].x + v[j].y * v[j].y + v[j].z * v[j].z + v[j].w * v[j].w;
    }
#pragma unroll
    for (int o = 16; o; o >>= 1) ss += __shfl_xor_sync(~0u, ss, o);
    float rstd = rsqrtf(ss / (float)DD + EPSF);
    float4* xo = (float4*)(g_xn + (size_t)t * DD);
    float s2 = 0.f;
#pragma unroll
    for (int j = 0; j < 6; j++) {
        float4 w = wr[lane + 32 * j];
        float4 a;
        a.x = v[j].x * rstd * w.x; a.y = v[j].y * rstd * w.y;
        a.z = v[j].z * rstd * w.z; a.w = v[j].w * rstd * w.w;
        xo[lane + 32 * j] = a;
        s2 += a.x * a.x + a.y * a.y + a.z * a.z + a.w * a.w;
    }
#pragma unroll
    for (int o = 16; o; o >>= 1) s2 += __shfl_xor_sync(~0u, s2, o);
    if (lane == 0) g_rn[t] = 1.f / fmaxf(sqrtf(s2), EPSF);
}

// ---------------- K2: logits, 2 tokens/thread, f32x2 ---------------------------
__global__ void __launch_bounds__(128) k_logits() {
    int t0 = blockIdx.x * 256 + threadIdx.x;
    int h = blockIdx.y, b = blockIdx.z;
    __shared__ float slS[MM][HD];
    for (int i = threadIdx.x; i < MM * (HD / 4); i += 128) {
        int m = i >> 4, d4 = i & 15;
        *(float4*)&slS[m][d4 * 4] = *(const float4*)&g_sl[m * DD + h * HD + d4 * 4];
    }
    __syncthreads();
    ull ta[32], tb[32];
    {
        float rn0 = g_rn[b * SS + t0];
        const float* xp = &g_xn[((size_t)(b * SS + t0)) * DD + h * HD];
#pragma unroll
        for (int i = 0; i < 16; i++) {
            float4 v = *(const float4*)(xp + i * 4);
            ta[2 * i] = pk2(v.x * rn0, v.y * rn0);
            ta[2 * i + 1] = pk2(v.z * rn0, v.w * rn0);
        }
        float rn1 = g_rn[b * SS + t0 + 128];
        const float* xq = &g_xn[((size_t)(b * SS + t0 + 128)) * DD + h * HD];
#pragma unroll
        for (int i = 0; i < 16; i++) {
            float4 v = *(const float4*)(xq + i * 4);
            tb[2 * i] = pk2(v.x * rn1, v.y * rn1);
            tb[2 * i + 1] = pk2(v.z * rn1, v.w * rn1);
        }
    }
    size_t lbase = (size_t)((b * HH + h) * MM) * SS;
    for (int m = 0; m < MM; m++) {
        ull a0 = 0, a1 = 0, c0 = 0, c1 = 0;
#pragma unroll
        for (int j = 0; j < 16; j++) {
            float4 sv = *(const float4*)&slS[m][j * 4];
            ull s0 = pk2(sv.x, sv.y), s1 = pk2(sv.z, sv.w);
            FMA2(a0, ta[2 * j], s0); FMA2(a1, ta[2 * j + 1], s1);
            FMA2(c0, tb[2 * j], s0); FMA2(c1, tb[2 * j + 1], s1);
        }
        float p0, p1, q0, q1, r0, r1, u0, u1;
        upk2(a0, p0, p1); upk2(a1, q0, q1);
        upk2(c0, r0, r1); upk2(c1, u0, u1);
        g_lh[lbase + (size_t)m * SS + t0]       = __float2half((p0 + p1) + (q0 + q1));
        g_lh[lbase + (size_t)m * SS + t0 + 128] = __float2half((r0 + r1) + (u0 + u1));
    }
}

// ---------------- K3: one-pass softmax stats -----------------------------------
__global__ void __launch_bounds__(128) k_stats() {
    int r = blockIdx.x, tid = threadIdx.x;
    const __half* row = g_lh + (size_t)r * SS;
    float4 raw[4];
    const float4* p = (const float4*)(row + tid * 32);
#pragma unroll
    for (int q = 0; q < 4; q++) raw[q] = p[q];
    float v[32];
#pragma unroll
    for (int q = 0; q < 4; q++) {
        const __half2* h2 = (const __half2*)&raw[q];
#pragma unroll
        for (int j = 0; j < 4; j++) {
            float2 f = __half22float2(h2[j]);
            v[q * 8 + j * 2] = f.x; v[q * 8 + j * 2 + 1] = f.y;
        }
    }
    float mx = -1e30f;
#pragma unroll
    for (int i = 0; i < 32; i++) mx = fmaxf(mx, v[i]);
    __shared__ float red[4];
    __shared__ float smxv;
    for (int o = 16; o; o >>= 1) mx = fmaxf(mx, __shfl_down_sync(~0u, mx, o));
    if ((tid & 31) == 0) red[tid >> 5] = mx;
    __syncthreads();
    if (tid == 0) smxv = fmaxf(fmaxf(red[0], red[1]), fmaxf(red[2], red[3]));
    __syncthreads();
    float gmx = smxv;
    float sm = 0.f;
#pragma unroll
    for (int i = 0; i < 32; i++) sm += __expf(v[i] - gmx);
    for (int o = 16; o; o >>= 1) sm += __shfl_down_sync(~0u, sm, o);
    __syncthreads();
    if ((tid & 31) == 0) red[tid >> 5] = sm;
    __syncthreads();
    if (tid == 0) {
        g_rmax[r] = gmx;
        g_rsum[r] = red[0] + red[1] + red[2] + red[3];
    }
}

// ---------------- K4: init -----------------------------------------------------
__global__ void k_binit(const float* __restrict__ b1, const float* __restrict__ b2) {
    int i = blockIdx.x * 256 + threadIdx.x;
    const int N1 = BB * MM * DD;
    const int N2 = BB * MM * FF;
    if (i < N1) g_y[i] = 0.f;
    else if (i < N1 + N2) { int k = i - N1; g_hid[k] = b1[k % (MM * FF)]; }
    else { int k = i - N1 - N2; g_y2[k] = b2[k % (MM * DD)]; }
}

// ---------------- K5: dispatch, dup-pair smem, f32x2 -----------------------------
__global__ void __launch_bounds__(128) k_disp() {
    int ch = blockIdx.x, h = blockIdx.y, b = blockIdx.z;
    int tid = threadIdx.x;
    int sp = tid >> 6;
    int w  = tid & 63;
    int mg = w >> 4;
    int dg = w & 15;
    __shared__ float2 pT2[64][66];   // [s][m] dup pairs
    __shared__ float xts[64][68];
    __shared__ float smax[64], sinv[64];
    if (tid < 64) {
        int r = (b * HH + h) * MM + tid;
        smax[tid] = g_rmax[r];
        sinv[tid] = 1.f / g_rsum[r];
    }
    ull accL[16], accH[16];
#pragma unroll
    for (int j = 0; j < 16; j++) { accL[j] = 0ull; accH[j] = 0ull; }
    size_t lbh = (size_t)((b * HH + h) * MM) * SS;
    int fm4 = (tid & 15) * 4;    // fill: 4 m rows
    int fsh = tid >> 4;          // fill: s-octet 0..7
    for (int tile = 0; tile < 8; tile++) {
        int s0 = (ch * 8 + tile) * 64;
        __syncthreads();
#pragma unroll
        for (int mi = 0; mi < 4; mi++) {
            int m = fm4 + mi;
            float mmax = smax[m], minv = sinv[m];
            float4 raw = *(const float4*)&g_lh[lbh + (size_t)m * SS + s0 + fsh * 8];
            const __half2* h2 = (const __half2*)&raw;
#pragma unroll
            for (int q = 0; q < 4; q++) {
                float2 f = __half22float2(h2[q]);
                float e0 = __expf(f.x - mmax) * minv;
                float e1 = __expf(f.y - mmax) * minv;
                pT2[fsh * 8 + 2 * q][m]     = make_float2(e0, e0);
                pT2[fsh * 8 + 2 * q + 1][m] = make_float2(e1, e1);
            }
        }
        for (int i = tid; i < 64 * 16; i += 128) {
            int s = i >> 4, d4 = i & 15;
            *(float4*)&xts[s][d4 * 4] =
                *(const float4*)&g_xn[((size_t)(b * SS + s0 + s)) * DD + h * HD + d4 * 4];
        }
        __syncthreads();
#pragma unroll 2
        for (int s = sp; s < 64; s += 2) {
            float4 xv = *(const float4*)&xts[s][dg * 4];
            ull xlo = pk2(xv.x, xv.y), xhi = pk2(xv.z, xv.w);
#pragma unroll
            for (int j = 0; j < 4; j++) {
                float4 pa = *(const float4*)&pT2[s][mg * 16 + j * 4];      // (m0,m0,m1,m1)
                float4 pb = *(const float4*)&pT2[s][mg * 16 + j * 4 + 2];  // (m2,m2,m3,m3)
                ull p0 = pk2(pa.x, pa.y), p1 = pk2(pa.z, pa.w);
                ull p2 = pk2(pb.x, pb.y), p3 = pk2(pb.z, pb.w);
                FMA2(accL[j * 4 + 0], p0, xlo); FMA2(accH[j * 4 + 0], p0, xhi);
                FMA2(accL[j * 4 + 1], p1, xlo); FMA2(accH[j * 4 + 1], p1, xhi);
                FMA2(accL[j * 4 + 2], p2, xlo); FMA2(accH[j * 4 + 2], p2, xhi);
                FMA2(accL[j * 4 + 3], p3, xlo); FMA2(accH[j * 4 + 3], p3, xhi);
            }
        }
    }
#pragma unroll
    for (int ml = 0; ml < 16; ml++) {
        int m = mg * 16 + ml;
        float a0, a1, a2, a3;
        upk2(accL[ml], a0, a1); upk2(accH[ml], a2, a3);
        float* base = &g_y[((size_t)(b * MM + m)) * DD + h * HD + dg * 4];
        atomicAdd(base + 0, a0);
        atomicAdd(base + 1, a1);
        atomicAdd(base + 2, a2);
        atomicAdd(base + 3, a3);
    }
}

// ---------------- K6: fc1, batch-pair f32x2 --------------------------------------
__global__ void __launch_bounds__(256) k_fc1(const float* __restrict__ w1) {
    int fblk = blockIdx.x, m = blockIdx.y, kc = blockIdx.z;
    int tid = threadIdx.x;
    int f = fblk * 1024 + tid * 4;
    __shared__ float ysT[384][12];   // [k][batch0..7], 48B rows
    for (int i = tid; i < 8 * 384; i += 256) {
        int bb = i / 384, k = i % 384;
        ysT[k][bb] = g_y[((size_t)(bb * MM + m)) * DD + kc * 384 + k];
    }
    __syncthreads();
    ull acc[4][4];   // [fi][bpair]
#pragma unroll
    for (int i = 0; i < 4; i++)
#pragma unroll
        for (int j = 0; j < 4; j++) acc[i][j] = 0ull;
    const float* wp = w1 + (size_t)m * DD * FF + (size_t)(kc * 384) * FF + f;
#pragma unroll 4
    for (int k = 0; k < 384; k++) {
        float4 wv = *(const float4*)(wp + (size_t)k * FF);
        float4 ya = *(const float4*)&ysT[k][0];
        float4 yb = *(const float4*)&ysT[k][4];
        ull y01 = pk2(ya.x, ya.y), y23 = pk2(ya.z, ya.w);
        ull y45 = pk2(yb.x, yb.y), y67 = pk2(yb.z, yb.w);
        ull w0 = pk2(wv.x, wv.x), w1d = pk2(wv.y, wv.y);
        ull w2 = pk2(wv.z, wv.z), w3 = pk2(wv.w, wv.w);
        FMA2(acc[0][0], w0, y01); FMA2(acc[0][1], w0, y23); FMA2(acc[0][2], w0, y45); FMA2(acc[0][3], w0, y67);
        FMA2(acc[1][0], w1d, y01); FMA2(acc[1][1], w1d, y23); FMA2(acc[1][2], w1d, y45); FMA2(acc[1][3], w1d, y67);
        FMA2(acc[2][0], w2, y01); FMA2(acc[2][1], w2, y23); FMA2(acc[2][2], w2, y45); FMA2(acc[2][3], w2, y67);
        FMA2(acc[3][0], w3, y01); FMA2(acc[3][1], w3, y23); FMA2(acc[3][2], w3, y45); FMA2(acc[3][3], w3, y67);
    }
#pragma unroll
    for (int fi = 0; fi < 4; fi++)
#pragma unroll
        for (int bp = 0; bp < 4; bp++) {
            float a0, a1;
            upk2(acc[fi][bp], a0, a1);
            atomicAdd(&g_hid[((size_t)((2 * bp) * MM + m)) * FF + f + fi], a0);
            atomicAdd(&g_hid[((size_t)((2 * bp + 1) * MM + m)) * FF + f + fi], a1);
        }
}

// ---------------- K7: fc2 (gelu on load), batch-pair f32x2 -----------------------
__global__ void __launch_bounds__(192) k_fc2(const float* __restrict__ w2) {
    int m = blockIdx.x, kc = blockIdx.y;
    int tid = threadIdx.x;
    int d = tid * 4;
    __shared__ float hsT[384][12];
    for (int i = tid; i < 8 * 384; i += 192) {
        int bb = i / 384, k = i % 384;
        float v = g_hid[((size_t)(bb * MM + m)) * FF + kc * 384 + k];
        hsT[k][bb] = 0.5f * v * (1.f + erff(v * 0.70710678118654752f));
    }
    __syncthreads();
    ull acc[4][4];
#pragma unroll
    for (int i = 0; i < 4; i++)
#pragma unroll
        for (int j = 0; j < 4; j++) acc[i][j] = 0ull;
    const float* wp = w2 + (size_t)m * FF * DD + (size_t)(kc * 384) * DD + d;
#pragma unroll 4
    for (int k = 0; k < 384; k++) {
        float4 wv = *(const float4*)(wp + (size_t)k * DD);
        float4 ya = *(const float4*)&hsT[k][0];
        float4 yb = *(const float4*)&hsT[k][4];
        ull y01 = pk2(ya.x, ya.y), y23 = pk2(ya.z, ya.w);
        ull y45 = pk2(yb.x, yb.y), y67 = pk2(yb.z, yb.w);
        ull w0 = pk2(wv.x, wv.x), w1d = pk2(wv.y, wv.y);
        ull w2d = pk2(wv.z, wv.z), w3 = pk2(wv.w, wv.w);
        FMA2(acc[0][0], w0, y01); FMA2(acc[0][1], w0, y23); FMA2(acc[0][2], w0, y45); FMA2(acc[0][3], w0, y67);
        FMA2(acc[1][0], w1d, y01); FMA2(acc[1][1], w1d, y23); FMA2(acc[1][2], w1d, y45); FMA2(acc[1][3], w1d, y67);
        FMA2(acc[2][0], w2d, y01); FMA2(acc[2][1], w2d, y23); FMA2(acc[2][2], w2d, y45); FMA2(acc[2][3], w2d, y67);
        FMA2(acc[3][0], w3, y01); FMA2(acc[3][1], w3, y23); FMA2(acc[3][2], w3, y45); FMA2(acc[3][3], w3, y67);
    }
#pragma unroll
    for (int di = 0; di < 4; di++)
#pragma unroll
        for (int bp = 0; bp < 4; bp++) {
            float a0, a1;
            upk2(acc[di][bp], a0, a1);
            atomicAdd(&g_y2[((size_t)((2 * bp) * MM + m)) * DD + d + di], a0);
            atomicAdd(&g_y2[((size_t)((2 * bp + 1) * MM + m)) * DD + d + di], a1);
        }
}

// ---------------- K8: combine, dup-pair smem, f32x2 -------------------------------
__global__ void __launch_bounds__(128) k_comb(float* __restrict__ out) {
    int sb = blockIdx.x, h = blockIdx.y, b = blockIdx.z;
    int s0 = sb * 64;
    int tid = threadIdx.x;
    __shared__ float2 pDup[64][66];   // [m][s] dup pairs
    __shared__ float y2s[64][72];
    __shared__ float pmax[2][64], psum[2][64], smx[64], sinvs[64];
    size_t lbh = (size_t)((b * HH + h) * MM) * SS;
    for (int i = tid; i < 64 * 32; i += 128) {
        int m = i >> 5, s2 = i & 31;
        __half2 hv = *(const __half2*)&g_lh[lbh + (size_t)m * SS + s0 + 2 * s2];
        float2 f = __half22float2(hv);
        float4 dup = make_float4(f.x, f.x, f.y, f.y);
        *(float4*)&pDup[m][2 * s2] = dup;
    }
    for (int i = tid; i < 64 * 16; i += 128) {
        int m = i >> 4, d4 = i & 15;
        *(float4*)&y2s[m][d4 * 4] =
            *(const float4*)&g_y2[((size_t)(b * MM + m)) * DD + h * HD + d4 * 4];
    }
    __syncthreads();
    {
        int t = tid & 63, mh = tid >> 6;
        float mx = -1e30f;
#pragma unroll 8
        for (int mm = 0; mm < 32; mm++) mx = fmaxf(mx, pDup[mh * 32 + mm][t].x);
        pmax[mh][t] = mx;
    }
    __syncthreads();
    if (tid < 64) smx[tid] = fmaxf(pmax[0][tid], pmax[1][tid]);
    __syncthreads();
    {
        int t = tid & 63, mh = tid >> 6;
        float mx = smx[t], sm = 0.f;
#pragma unroll 8
        for (int mm = 0; mm < 32; mm++) {
            float e = __expf(pDup[mh * 32 + mm][t].x - mx);
            pDup[mh * 32 + mm][t] = make_float2(e, e);
            sm += e;
        }
        psum[mh][t] = sm;
    }
    __syncthreads();
    if (tid < 64) sinvs[tid] = 1.f / (psum[0][tid] + psum[1][tid]);
    __syncthreads();
    int sg = tid >> 3, dgrp = tid & 7;
    ull acc[4][4];
#pragma unroll
    for (int i = 0; i < 4; i++)
#pragma unroll
        for (int j = 0; j < 4; j++) acc[i][j] = 0ull;
#pragma unroll 4
    for (int m = 0; m < 64; m++) {
        float4 pa = *(const float4*)&pDup[m][sg * 4];      // (s0,s0,s1,s1)
        float4 pb = *(const float4*)&pDup[m][sg * 4 + 2];  // (s2,s2,s3,s3)
        ull pd0 = pk2(pa.x, pa.y), pd1 = pk2(pa.z, pa.w);
        ull pd2 = pk2(pb.x, pb.y), pd3 = pk2(pb.z, pb.w);
        float4 ya = *(const float4*)&y2s[m][dgrp * 8];
        float4 yb = *(const float4*)&y2s[m][dgrp * 8 + 4];
        ull yv0 = pk2(ya.x, ya.y), yv1 = pk2(ya.z, ya.w);
        ull yv2 = pk2(yb.x, yb.y), yv3 = pk2(yb.z, yb.w);
        FMA2(acc[0][0], pd0, yv0); FMA2(acc[0][1], pd0, yv1); FMA2(acc[0][2], pd0, yv2); FMA2(acc[0][3], pd0, yv3);
        FMA2(acc[1][0], pd1, yv0); FMA2(acc[1][1], pd1, yv1); FMA2(acc[1][2], pd1, yv2); FMA2(acc[1][3], pd1, yv3);
        FMA2(acc[2][0], pd2, yv0); FMA2(acc[2][1], pd2, yv1); FMA2(acc[2][2], pd2, yv2); FMA2(acc[2][3], pd2, yv3);
        FMA2(acc[3][0], pd3, yv0); FMA2(acc[3][1], pd3, yv1); FMA2(acc[3][2], pd3, yv2); FMA2(acc[3][3], pd3, yv3);
    }
#pragma unroll
    for (int ss = 0; ss < 4; ss++) {
        int s = s0 + sg * 4 + ss;
        float inv = sinvs[sg * 4 + ss];
        float o0, o1, o2, o3, o4, o5, o6, o7;
        upk2(acc[ss][0], o0, o1); upk2(acc[ss][1], o2, o3);
        upk2(acc[ss][2], o4, o5); upk2(acc[ss][3], o6, o7);
        float* op = &out[((size_t)(b * SS + s)) * DD + h * HD + dgrp * 8];
        float4 w0 = make_float4(o0 * inv, o1 * inv, o2 * inv, o3 * inv);
        float4 w1 = make_float4(o4 * inv, o5 * inv, o6 * inv, o7 * inv);
        *(float4*)(op + 0) = w0;
        *(float4*)(op + 4) = w1;
    }
}

// ---------------- launch --------------------------------------------------------
extern "C" void kernel_launch(void* const* d_in, const int* in_sizes, int n_in,
                              void* d_out, int out_size) {
    const float* x      = (const float*)d_in[0];
    const float* slots  = (const float*)d_in[1];
    const float* scale  = (const float*)d_in[2];
    const float* fc1_w  = (const float*)d_in[3];
    const float* fc1_b  = (const float*)d_in[4];
    const float* fc2_w  = (const float*)d_in[5];
    const float* fc2_b  = (const float*)d_in[6];
    const float* norm_w = (const float*)d_in[7];
    float* out = (float*)d_out;

    k_slots<<<MM, 256>>>(slots, scale);
    k_norm<<<BB * SS / 8, 256>>>(x, norm_w);
    k_logits<<<dim3(SS / 256, HH, BB), 128>>>();
    k_stats<<<BB * HH * MM, 128>>>();
    k_binit<<<(BB * MM * (2 * DD + FF)) / 256, 256>>>(fc1_b, fc2_b);
    k_disp<<<dim3(8, HH, BB), 128>>>();
    k_fc1<<<dim3(3, MM, 2), 256>>>(fc1_w);
    k_fc2<<<dim3(MM, 8), 192>>>(fc2_w);
    k_comb<<<dim3(SS / 64, HH, BB), 128>>>(out);
}